// round 16
// baseline (speedup 1.0000x reference)
#include <cuda_runtime.h>
#include <cstdint>
#include <cstddef>

constexpr int H = 4096, B = 32, G4 = 16384;      // hidden, batch, 4H
constexpr int BH = B * H;                        // 131072
constexpr int LAYER_W = G4 * H;                  // weight elems per layer-matrix
constexpr int KSTEPS = H / 16;                   // 256 k16 steps per matrix
constexpr int CH = 8;                            // ksteps per smem chunk (128 floats of K)
constexpr int NCHP = KSTEPS / CH;                // 32 chunks per pass
constexpr int NCH = 2 * NCHP;                    // 64 chunks total (ih pass + hh pass)

// ---- smem layout (bytes, per stage) ---- (m64 tile)
constexpr int A_STRIDE_F = 132;                  // 128 + 4 pad floats
constexpr int A_STRIDE_B = A_STRIDE_F * 4;       // 528
constexpr int A_BYTES = 64 * A_STRIDE_B;         // 33792
constexpr int B_OFF   = A_BYTES;
constexpr int B_BYTES = CH * 32 * 4 * 16;        // 16384
constexpr int STAGE   = A_BYTES + B_BYTES;       // 50176
constexpr int SMEM_TOTAL = 2 * STAGE;            // 100352  (2 CTAs/SM)

// ---- scratch (device globals; no allocation) ----
__device__ float g_gates[(size_t)G4 * B];        // 2 MB
__device__ uint4 g_xfrag[2][KSTEPS * B * 4];     // input-act frags per layer
__device__ uint4 g_hfrag[2][KSTEPS * B * 4];     // hidden-act frags per layer
__device__ float g_hnew[BH];                     // layer-0 h_new (fp32)

// ---- helpers ----
__device__ __forceinline__ void split2(float2 p, uint32_t& h, uint32_t& l) {
    uint32_t u0 = __float_as_uint(p.x), u1 = __float_as_uint(p.y);
    h = __byte_perm(u0, u1, 0x7632);
    float l0 = p.x - __uint_as_float(u0 & 0xFFFF0000u);
    float l1 = p.y - __uint_as_float(u1 & 0xFFFF0000u);
    asm("cvt.rn.bf16x2.f32 %0, %1, %2;" : "=r"(l) : "f"(l1), "f"(l0));
}

__device__ __forceinline__ void mma16816(float* d, const uint32_t* a, uint32_t b0, uint32_t b1) {
    asm volatile(
        "mma.sync.aligned.m16n8k16.row.col.f32.bf16.bf16.f32 "
        "{%0,%1,%2,%3}, {%4,%5,%6,%7}, {%8,%9}, {%0,%1,%2,%3};\n"
        : "+f"(d[0]), "+f"(d[1]), "+f"(d[2]), "+f"(d[3])
        : "r"(a[0]), "r"(a[1]), "r"(a[2]), "r"(a[3]), "r"(b0), "r"(b1));
}

#define CP_ASYNC16(smaddr, gptr) \
    asm volatile("cp.async.cg.shared.global [%0], [%1], 16;" :: "r"(smaddr), "l"(gptr) : "memory")
#define CP_COMMIT()  asm volatile("cp.async.commit_group;" ::: "memory")
#define CP_WAIT1()   asm volatile("cp.async.wait_group 1;" ::: "memory")
#define CP_WAIT0()   asm volatile("cp.async.wait_group 0;" ::: "memory")

// ---- prep: fp32 activations -> frag-ordered bf16 hi/lo ----
__global__ void prep3_kernel(const float* __restrict__ x, const float* __restrict__ h) {
    int idx = blockIdx.x * blockDim.x + threadIdx.x;        // 0..98303
    int i2 = idx & 32767;
    const float* s;
    uint4* d;
    if (idx < 32768)      { s = x;      d = g_xfrag[0]; }
    else if (idx < 65536) { s = h;      d = g_hfrag[0]; }
    else                  { s = h + BH; d = g_hfrag[1]; }
    int t4 = i2 & 3, n = (i2 >> 2) & 31, c = i2 >> 7;
    int k0 = c * 16 + 2 * t4;
    float2 p0 = *(const float2*)&s[(size_t)n * H + k0];
    float2 p1 = *(const float2*)&s[(size_t)n * H + k0 + 8];
    uint4 v;
    split2(p0, v.x, v.z);
    split2(p1, v.y, v.w);
    d[i2] = v;
}

// g_hnew -> g_xfrag[1]
__global__ void prep1_kernel() {
    int i2 = blockIdx.x * blockDim.x + threadIdx.x;         // 0..32767
    int t4 = i2 & 3, n = (i2 >> 2) & 31, c = i2 >> 7;
    int k0 = c * 16 + 2 * t4;
    float2 p0 = *(const float2*)&g_hnew[(size_t)n * H + k0];
    float2 p1 = *(const float2*)&g_hnew[(size_t)n * H + k0 + 8];
    uint4 v;
    split2(p0, v.x, v.z);
    split2(p1, v.y, v.w);
    g_xfrag[1][i2] = v;
}

// ---- GEMM: gates = Wih@x^T + Whh@h^T + bih + bhh ----
// grid=256 CTAs, 128 threads (4 warps), 2 CTAs/SM. CTA owns 64 contiguous gate
// rows. Warp (rg, kh): rg = wid&1 -> rows rg*32..rg*32+31, kh = wid>>1 ->
// ksteps [kh*4, kh*4+4) of each chunk. K-half partial sums reduced via smem.
__global__ void __launch_bounds__(128, 2) gemm_kernel(
    const float* __restrict__ Wih, const float* __restrict__ Whh,
    const float* __restrict__ bih, const float* __restrict__ bhh,
    const uint4* __restrict__ Fx, const uint4* __restrict__ Fh)
{
    extern __shared__ char smem[];
    const int tid = threadIdx.x, lane = tid & 31, wid = tid >> 5;
    const int g = lane >> 2, t4 = lane & 3;
    const int rg = wid & 1, kh = wid >> 1;
    const int m_base = blockIdx.x * 64;

    float acc[2][4][4] = {};                          // [m16 tile][n8 tile][frag]

    // stage chunk ch (0..63) into buffer (ch&1)  -- identical to R14
    auto stage = [&](int ch) {
        const int pass = ch >> 5, cc = ch & 31;
        const float* W = pass ? Whh : Wih;
        const uint4* F = pass ? Fh : Fx;
        char* sb = smem + (ch & 1) * STAGE;
        #pragma unroll
        for (int i = 0; i < 16; ++i) {
            int s = tid + i * 128;
            int row = s >> 5, seg = s & 31;
            const float* gp = W + (size_t)(m_base + row) * H + cc * 128 + seg * 4;
            const void* gg = (const void*)__cvta_generic_to_global((void*)gp);
            uint32_t sa;
            asm("{ .reg .u64 t; cvta.to.shared.u64 t, %1; cvt.u32.u64 %0, t; }"
                : "=r"(sa) : "l"(sb + row * A_STRIDE_B + seg * 16));
            CP_ASYNC16(sa, gg);
        }
        #pragma unroll
        for (int i = 0; i < 8; ++i) {
            int s = tid + i * 128;
            const void* gg = (const void*)__cvta_generic_to_global((void*)(F + (size_t)cc * 1024 + s));
            uint32_t sa;
            asm("{ .reg .u64 t; cvta.to.shared.u64 t, %1; cvt.u32.u64 %0, t; }"
                : "=r"(sa) : "l"(sb + B_OFF + s * 16));
            CP_ASYNC16(sa, gg);
        }
        CP_COMMIT();
    };

    stage(0);
    stage(1);

    #pragma unroll 1
    for (int ch = 0; ch < NCH; ++ch) {
        if (ch + 1 < NCH) { CP_WAIT1(); } else { CP_WAIT0(); }
        __syncthreads();

        const char* sb = smem + (ch & 1) * STAGE;
        // warp's 4 A-row bases: rows rg*32 + {g, g+8, g+16, g+24}
        const char* rA[4];
        #pragma unroll
        for (int mi2 = 0; mi2 < 4; ++mi2)
            rA[mi2] = sb + (size_t)(rg * 32 + mi2 * 8 + g) * A_STRIDE_B;
        const uint4* sB = (const uint4*)(sb + B_OFF);

        #pragma unroll
        for (int q = 0; q < 4; ++q) {
            const int kk = kh * 4 + q;
            const int col = kk * 16 + 2 * t4;

            uint32_t ah[2][4], al[2][4];
            #pragma unroll
            for (int mi = 0; mi < 2; ++mi) {
                float2 a0 = *(const float2*)(rA[2 * mi + 0] + col * 4);
                float2 a1 = *(const float2*)(rA[2 * mi + 1] + col * 4);
                float2 a2 = *(const float2*)(rA[2 * mi + 0] + (col + 8) * 4);
                float2 a3 = *(const float2*)(rA[2 * mi + 1] + (col + 8) * 4);
                split2(a0, ah[mi][0], al[mi][0]);
                split2(a1, ah[mi][1], al[mi][1]);
                split2(a2, ah[mi][2], al[mi][2]);
                split2(a3, ah[mi][3], al[mi][3]);
            }

            uint4 bb[4];
            #pragma unroll
            for (int t = 0; t < 4; ++t)
                bb[t] = sB[kk * 128 + (8 * t + g) * 4 + t4];   // {bh0,bh1,bl0,bl1}

            // term-outer, 8 independent acc chains between dependent MMAs
            #pragma unroll
            for (int t = 0; t < 4; ++t) {
                mma16816(acc[0][t], ah[0], bb[t].x, bb[t].y);
                mma16816(acc[1][t], ah[1], bb[t].x, bb[t].y);
            }
            #pragma unroll
            for (int t = 0; t < 4; ++t) {
                mma16816(acc[0][t], ah[0], bb[t].z, bb[t].w);
                mma16816(acc[1][t], ah[1], bb[t].z, bb[t].w);
            }
            #pragma unroll
            for (int t = 0; t < 4; ++t) {
                mma16816(acc[0][t], al[0], bb[t].x, bb[t].y);
                mma16816(acc[1][t], al[1], bb[t].x, bb[t].y);
            }
        }
        __syncthreads();
        if (ch + 2 < NCH) stage(ch + 2);
    }

    // ---- reduce K-halves via smem (8 KB), then bias + write gates ----
    float* red = (float*)smem;    // [rg][mi][t][lane][4] : 2*2*4*32*4 floats
    if (kh == 1) {
        #pragma unroll
        for (int mi = 0; mi < 2; ++mi)
            #pragma unroll
            for (int t = 0; t < 4; ++t)
                *(float4*)&red[(((rg * 2 + mi) * 4 + t) * 32 + lane) * 4] =
                    *(float4*)acc[mi][t];
    }
    __syncthreads();
    if (kh == 0) {
        #pragma unroll
        for (int mi = 0; mi < 2; ++mi) {
            #pragma unroll
            for (int t = 0; t < 4; ++t) {
                float4 v = *(const float4*)&red[(((rg * 2 + mi) * 4 + t) * 32 + lane) * 4];
                acc[mi][t][0] += v.x;  acc[mi][t][1] += v.y;
                acc[mi][t][2] += v.z;  acc[mi][t][3] += v.w;
            }
        }
        #pragma unroll
        for (int mi = 0; mi < 2; ++mi) {
            const int j0 = m_base + rg * 32 + mi * 16 + g;
            const float bi0 = bih[j0] + bhh[j0];
            const float bi1 = bih[j0 + 8] + bhh[j0 + 8];
            #pragma unroll
            for (int t = 0; t < 4; ++t) {
                int colb = 8 * t + 2 * t4;
                *(float2*)&g_gates[(size_t)j0 * B + colb] =
                    make_float2(acc[mi][t][0] + bi0, acc[mi][t][1] + bi0);
                *(float2*)&g_gates[(size_t)(j0 + 8) * B + colb] =
                    make_float2(acc[mi][t][2] + bi1, acc[mi][t][3] + bi1);
            }
        }
    }
}

// ---- LSTM cell (elementwise) ----
__global__ void cell_kernel(const float* __restrict__ prev_c, float* __restrict__ out, int l) {
    int idx = blockIdx.x * blockDim.x + threadIdx.x;         // b*H + h
    int h = idx & (H - 1), b = idx >> 12;
    float gi = g_gates[(size_t)h * B + b];
    float gf = g_gates[(size_t)(H + h) * B + b];
    float gg = g_gates[(size_t)(2 * H + h) * B + b];
    float go = g_gates[(size_t)(3 * H + h) * B + b];
    float si = 1.f / (1.f + expf(-gi));
    float sf = 1.f / (1.f + expf(-gf));
    float so = 1.f / (1.f + expf(-go));
    float c = prev_c[(size_t)l * BH + idx];
    float cn = sf * c + si * tanhf(gg);
    float hn = so * tanhf(cn);
    out[(size_t)(0 * 2 + l) * BH + idx] = hn;                // next_h
    out[(size_t)(1 * 2 + l) * BH + idx] = cn;                // next_c
    if (l == 0) g_hnew[idx] = hn;                            // feeds layer 1
}

// ---- launch ----
extern "C" void kernel_launch(void* const* d_in, const int* in_sizes, int n_in,
                              void* d_out, int out_size) {
    const float* inputs = (const float*)d_in[0];
    const float* prev_h = (const float*)d_in[1];
    const float* prev_c = (const float*)d_in[2];
    const float* W_ih   = (const float*)d_in[3];
    const float* W_hh   = (const float*)d_in[4];
    const float* b_ih   = (const float*)d_in[5];
    const float* b_hh   = (const float*)d_in[6];
    float* out = (float*)d_out;

    cudaFuncSetAttribute(gemm_kernel,
                         cudaFuncAttributeMaxDynamicSharedMemorySize, SMEM_TOTAL);

    uint4 *fx0, *fh0;
    cudaGetSymbolAddress((void**)&fx0, g_xfrag);
    cudaGetSymbolAddress((void**)&fh0, g_hfrag);
    uint4* fx1 = fx0 + KSTEPS * B * 4;
    uint4* fh1 = fh0 + KSTEPS * B * 4;

    // layer 0
    prep3_kernel<<<384, 256>>>(inputs, prev_h);
    gemm_kernel<<<256, 128, SMEM_TOTAL>>>(W_ih, W_hh, b_ih, b_hh, fx0, fh0);
    cell_kernel<<<512, 256>>>(prev_c, out, 0);
    // layer 1
    prep1_kernel<<<128, 256>>>();
    gemm_kernel<<<256, 128, SMEM_TOTAL>>>(W_ih + (size_t)LAYER_W, W_hh + (size_t)LAYER_W,
                                          b_ih + G4, b_hh + G4, fx1, fh1);
    cell_kernel<<<512, 256>>>(prev_c, out, 1);
}

// round 17
// speedup vs baseline: 1.1586x; 1.1586x over previous
#include <cuda_runtime.h>
#include <cstdint>
#include <cstddef>

constexpr int H = 4096, B = 32, G4 = 16384;      // hidden, batch, 4H
constexpr int BH = B * H;                        // 131072
constexpr int LAYER_W = G4 * H;                  // weight elems per layer-matrix
constexpr int KSTEPS = H / 16;                   // 256 k16 steps per matrix
constexpr int CH = 8;                            // ksteps per smem chunk (128 floats of K)
constexpr int NCHP = KSTEPS / CH;                // 32 chunks per pass
constexpr int NCH = 2 * NCHP;                    // 64 chunks total (ih pass + hh pass)

// ---- smem layout (bytes, per stage) ---- (m64 tile)
constexpr int A_STRIDE_F = 132;                  // 128 + 4 pad floats
constexpr int A_STRIDE_B = A_STRIDE_F * 4;       // 528
constexpr int A_BYTES = 64 * A_STRIDE_B;         // 33792
constexpr int B_OFF   = A_BYTES;
constexpr int B_BYTES = CH * 32 * 4 * 8;         // 8192 (uint2 frags)
constexpr int STAGE   = A_BYTES + B_BYTES;       // 41984
constexpr int SMEM_TOTAL = 2 * STAGE;            // 83968  (2 CTAs/SM)

// ---- scratch (device globals; no allocation) ----
__device__ float g_gates[(size_t)G4 * B];        // 2 MB
__device__ uint2 g_xfrag[2][KSTEPS * B * 4];     // input-act fp16 frags per layer
__device__ uint2 g_hfrag[2][KSTEPS * B * 4];     // hidden-act fp16 frags per layer
__device__ float g_hnew[BH];                     // layer-0 h_new (fp32)

// ---- helpers ----
// fp16 2-term split: h = rn_f16x2(p); l = rn_f16x2((p - h) * 1024)
__device__ __forceinline__ void split2h(float2 p, uint32_t& h, uint32_t& l) {
    uint32_t hh;
    asm("cvt.rn.f16x2.f32 %0, %1, %2;" : "=r"(hh) : "f"(p.y), "f"(p.x));  // lo=p.x
    float r0, r1;
    asm("{ .reg .b16 a, b; mov.b32 {a, b}, %2; cvt.f32.f16 %0, a; cvt.f32.f16 %1, b; }"
        : "=f"(r0), "=f"(r1) : "r"(hh));
    float l0 = (p.x - r0) * 1024.f, l1 = (p.y - r1) * 1024.f;
    asm("cvt.rn.f16x2.f32 %0, %1, %2;" : "=r"(l) : "f"(l1), "f"(l0));
    h = hh;
}
// plain fp16 convert (B side, no correction)
__device__ __forceinline__ uint32_t cvt2h(float2 p) {
    uint32_t r;
    asm("cvt.rn.f16x2.f32 %0, %1, %2;" : "=r"(r) : "f"(p.y), "f"(p.x));
    return r;
}

__device__ __forceinline__ void mma16816(float* d, const uint32_t* a, uint32_t b0, uint32_t b1) {
    asm volatile(
        "mma.sync.aligned.m16n8k16.row.col.f32.f16.f16.f32 "
        "{%0,%1,%2,%3}, {%4,%5,%6,%7}, {%8,%9}, {%0,%1,%2,%3};\n"
        : "+f"(d[0]), "+f"(d[1]), "+f"(d[2]), "+f"(d[3])
        : "r"(a[0]), "r"(a[1]), "r"(a[2]), "r"(a[3]), "r"(b0), "r"(b1));
}

#define CP_ASYNC16(smaddr, gptr) \
    asm volatile("cp.async.cg.shared.global [%0], [%1], 16;" :: "r"(smaddr), "l"(gptr) : "memory")
#define CP_COMMIT()  asm volatile("cp.async.commit_group;" ::: "memory")
#define CP_WAIT1()   asm volatile("cp.async.wait_group 1;" ::: "memory")
#define CP_WAIT0()   asm volatile("cp.async.wait_group 0;" ::: "memory")

// ---- prep: fp32 activations -> frag-ordered fp16 (hi only) ----
__global__ void prep3_kernel(const float* __restrict__ x, const float* __restrict__ h) {
    int idx = blockIdx.x * blockDim.x + threadIdx.x;        // 0..98303
    int i2 = idx & 32767;
    const float* s;
    uint2* d;
    if (idx < 32768)      { s = x;      d = g_xfrag[0]; }
    else if (idx < 65536) { s = h;      d = g_hfrag[0]; }
    else                  { s = h + BH; d = g_hfrag[1]; }
    int t4 = i2 & 3, n = (i2 >> 2) & 31, c = i2 >> 7;
    int k0 = c * 16 + 2 * t4;
    float2 p0 = *(const float2*)&s[(size_t)n * H + k0];
    float2 p1 = *(const float2*)&s[(size_t)n * H + k0 + 8];
    d[i2] = make_uint2(cvt2h(p0), cvt2h(p1));
}

// g_hnew -> g_xfrag[1]
__global__ void prep1_kernel() {
    int i2 = blockIdx.x * blockDim.x + threadIdx.x;         // 0..32767
    int t4 = i2 & 3, n = (i2 >> 2) & 31, c = i2 >> 7;
    int k0 = c * 16 + 2 * t4;
    float2 p0 = *(const float2*)&g_hnew[(size_t)n * H + k0];
    float2 p1 = *(const float2*)&g_hnew[(size_t)n * H + k0 + 8];
    g_xfrag[1][i2] = make_uint2(cvt2h(p0), cvt2h(p1));
}

// ---- GEMM: gates = Wih@x^T + Whh@h^T + bih + bhh ----
// grid=256 CTAs, 128 threads (4 warps), 2 CTAs/SM. CTA owns 64 contiguous gate
// rows; warp w owns rows m_base + w*16. Double-buffered cp.async over 64 chunks.
// fp16 2-term: acc1 += Wh*Xh ; acc2 += Wl2*Xh ; gates = acc1 + acc2/1024.
__global__ void __launch_bounds__(128, 2) gemm_kernel(
    const float* __restrict__ Wih, const float* __restrict__ Whh,
    const float* __restrict__ bih, const float* __restrict__ bhh,
    const uint2* __restrict__ Fx, const uint2* __restrict__ Fh)
{
    extern __shared__ char smem[];
    const int tid = threadIdx.x, lane = tid & 31, wid = tid >> 5;
    const int g = lane >> 2, t4 = lane & 3;
    const int m_base = blockIdx.x * 64;
    const int m0 = m_base + wid * 16;                 // warp's 16 rows

    float acc1[4][4] = {};                            // main term
    float acc2[4][4] = {};                            // W-correction term (x1024)

    // stage chunk ch (0..63) into buffer (ch&1)
    auto stage = [&](int ch) {
        const int pass = ch >> 5, cc = ch & 31;
        const float* W = pass ? Whh : Wih;
        const uint2* F = pass ? Fh : Fx;
        char* sb = smem + (ch & 1) * STAGE;
        // A: 64 rows x 512B, as 2048 x 16B segments
        #pragma unroll
        for (int i = 0; i < 16; ++i) {
            int s = tid + i * 128;
            int row = s >> 5, seg = s & 31;
            const float* gp = W + (size_t)(m_base + row) * H + cc * 128 + seg * 4;
            const void* gg = (const void*)__cvta_generic_to_global((void*)gp);
            uint32_t sa;
            asm("{ .reg .u64 t; cvta.to.shared.u64 t, %1; cvt.u32.u64 %0, t; }"
                : "=r"(sa) : "l"(sb + row * A_STRIDE_B + seg * 16));
            CP_ASYNC16(sa, gg);
        }
        // B: 512 x 16B (8 KB of uint2 frags)
        #pragma unroll
        for (int i = 0; i < 4; ++i) {
            int s = tid + i * 128;
            const void* gg = (const void*)__cvta_generic_to_global(
                (void*)((const uint4*)(F + (size_t)cc * 1024) + s));
            uint32_t sa;
            asm("{ .reg .u64 t; cvta.to.shared.u64 t, %1; cvt.u32.u64 %0, t; }"
                : "=r"(sa) : "l"(sb + B_OFF + s * 16));
            CP_ASYNC16(sa, gg);
        }
        CP_COMMIT();
    };

    stage(0);
    stage(1);

    #pragma unroll 1
    for (int ch = 0; ch < NCH; ++ch) {
        if (ch + 1 < NCH) { CP_WAIT1(); } else { CP_WAIT0(); }
        __syncthreads();

        const char* sb = smem + (ch & 1) * STAGE;
        const char* rowA0 = sb + (size_t)(wid * 16 + g) * A_STRIDE_B;        // row g
        const char* rowA1 = rowA0 + 8 * A_STRIDE_B;                          // row g+8
        const uint2* sB = (const uint2*)(sb + B_OFF);

        #pragma unroll
        for (int kk = 0; kk < CH; ++kk) {
            const int col = kk * 16 + 2 * t4;
            float2 a0 = *(const float2*)(rowA0 + col * 4);
            float2 a1 = *(const float2*)(rowA1 + col * 4);
            float2 a2 = *(const float2*)(rowA0 + (col + 8) * 4);
            float2 a3 = *(const float2*)(rowA1 + (col + 8) * 4);
            uint32_t ah[4], al[4];
            split2h(a0, ah[0], al[0]);
            split2h(a1, ah[1], al[1]);
            split2h(a2, ah[2], al[2]);
            split2h(a3, ah[3], al[3]);

            uint2 bb[4];
            #pragma unroll
            for (int t = 0; t < 4; ++t)
                bb[t] = sB[kk * 128 + (8 * t + g) * 4 + t4];   // {bh0, bh1}

            // 8 MMAs/kstep, 8 independent accumulator chains
            #pragma unroll
            for (int t = 0; t < 4; ++t) mma16816(acc1[t], ah, bb[t].x, bb[t].y);  // Wh*Xh
            #pragma unroll
            for (int t = 0; t < 4; ++t) mma16816(acc2[t], al, bb[t].x, bb[t].y);  // Wl2*Xh
        }
        __syncthreads();
        if (ch + 2 < NCH) stage(ch + 2);
    }

    // epilogue: fold correction, add biases, write gates[j][b]
    constexpr float INV = 1.0f / 1024.0f;
    const int j0 = m0 + g;
    const float bi0 = bih[j0] + bhh[j0];
    const float bi1 = bih[j0 + 8] + bhh[j0 + 8];
    #pragma unroll
    for (int t = 0; t < 4; ++t) {
        int colb = 8 * t + 2 * t4;
        *(float2*)&g_gates[(size_t)j0 * B + colb] =
            make_float2(acc1[t][0] + acc2[t][0] * INV + bi0,
                        acc1[t][1] + acc2[t][1] * INV + bi0);
        *(float2*)&g_gates[(size_t)(j0 + 8) * B + colb] =
            make_float2(acc1[t][2] + acc2[t][2] * INV + bi1,
                        acc1[t][3] + acc2[t][3] * INV + bi1);
    }
}

// ---- LSTM cell (elementwise) ----
__global__ void cell_kernel(const float* __restrict__ prev_c, float* __restrict__ out, int l) {
    int idx = blockIdx.x * blockDim.x + threadIdx.x;         // b*H + h
    int h = idx & (H - 1), b = idx >> 12;
    float gi = g_gates[(size_t)h * B + b];
    float gf = g_gates[(size_t)(H + h) * B + b];
    float gg = g_gates[(size_t)(2 * H + h) * B + b];
    float go = g_gates[(size_t)(3 * H + h) * B + b];
    float si = 1.f / (1.f + expf(-gi));
    float sf = 1.f / (1.f + expf(-gf));
    float so = 1.f / (1.f + expf(-go));
    float c = prev_c[(size_t)l * BH + idx];
    float cn = sf * c + si * tanhf(gg);
    float hn = so * tanhf(cn);
    out[(size_t)(0 * 2 + l) * BH + idx] = hn;                // next_h
    out[(size_t)(1 * 2 + l) * BH + idx] = cn;                // next_c
    if (l == 0) g_hnew[idx] = hn;                            // feeds layer 1
}

// ---- launch ----
extern "C" void kernel_launch(void* const* d_in, const int* in_sizes, int n_in,
                              void* d_out, int out_size) {
    const float* inputs = (const float*)d_in[0];
    const float* prev_h = (const float*)d_in[1];
    const float* prev_c = (const float*)d_in[2];
    const float* W_ih   = (const float*)d_in[3];
    const float* W_hh   = (const float*)d_in[4];
    const float* b_ih   = (const float*)d_in[5];
    const float* b_hh   = (const float*)d_in[6];
    float* out = (float*)d_out;

    cudaFuncSetAttribute(gemm_kernel,
                         cudaFuncAttributeMaxDynamicSharedMemorySize, SMEM_TOTAL);

    uint2 *fx0, *fh0;
    cudaGetSymbolAddress((void**)&fx0, g_xfrag);
    cudaGetSymbolAddress((void**)&fh0, g_hfrag);
    uint2* fx1 = fx0 + KSTEPS * B * 4;
    uint2* fh1 = fh0 + KSTEPS * B * 4;

    // layer 0
    prep3_kernel<<<384, 256>>>(inputs, prev_h);
    gemm_kernel<<<256, 128, SMEM_TOTAL>>>(W_ih, W_hh, b_ih, b_hh, fx0, fh0);
    cell_kernel<<<512, 256>>>(prev_c, out, 0);
    // layer 1
    prep1_kernel<<<128, 256>>>();
    gemm_kernel<<<256, 128, SMEM_TOTAL>>>(W_ih + (size_t)LAYER_W, W_hh + (size_t)LAYER_W,
                                          b_ih + G4, b_hh + G4, fx1, fh1);
    cell_kernel<<<512, 256>>>(prev_c, out, 1);
}